// round 3
// baseline (speedup 1.0000x reference)
#include <cuda_runtime.h>
#include <cstdint>

typedef unsigned long long ull;

#define RB 4            // batch elements per warp
#define WARPS 7         // warps per CTA
#define EPC (WARPS*RB)  // 28 elements per CTA
#define BB 4096
#define TT 2048

// smem layout (floats)
#define OFF_W  0        // [4 gates][2 slotpairs][100 kp][64 = 2*lane+half]  -> 51200
#define OFF_B  51200    // [4][128]
#define OFF_WX 51712    // [4][128]
#define OFF_W2 52224    // [4][128]
#define OFF_SM 52736    // whh2[0..3], b2sum[4..7]
#define SMEM_FLOATS 52744
#define SMEM_BYTES (SMEM_FLOATS*4)

__device__ __forceinline__ ull pk2(float lo, float hi) {
    ull r; asm("mov.b64 %0, {%1, %2};" : "=l"(r) : "f"(lo), "f"(hi)); return r;
}
__device__ __forceinline__ void upk2(ull v, float& lo, float& hi) {
    asm("mov.b64 {%0, %1}, %2;" : "=f"(lo), "=f"(hi) : "l"(v));
}
__device__ __forceinline__ ull fma2(ull a, ull b, ull c) {
    ull d; asm("fma.rn.f32x2 %0, %1, %2, %3;" : "=l"(d) : "l"(a), "l"(b), "l"(c)); return d;
}
__device__ __forceinline__ float sigf(float x) {
    float e = __expf(-x);
    return __fdividef(1.0f, 1.0f + e);
}
__device__ __forceinline__ float tahf(float x) {
    float a = fabsf(x);
    float E = __expf(2.0f * a);              // E in [1, inf]
    float t = 1.0f - __fdividef(2.0f, E + 1.0f);  // E=inf -> t=1, safe
    return (x < 0.0f) ? -t : t;
}

__global__ __launch_bounds__(WARPS*32, 1)
void lstm2_kernel(const float* __restrict__ input,
                  const float* __restrict__ W_ih1,
                  const float* __restrict__ W_hh1,
                  const float* __restrict__ b_ih1,
                  const float* __restrict__ b_hh1,
                  const float* __restrict__ W_ih2,
                  const float* __restrict__ W_hh2,
                  const float* __restrict__ b_ih2,
                  const float* __restrict__ b_hh2,
                  float* __restrict__ out)
{
    extern __shared__ float smem[];
    float* sW  = smem + OFF_W;
    float* sB  = smem + OFF_B;
    float* sWx = smem + OFF_WX;
    float* sW2 = smem + OFF_W2;
    float* sSm = smem + OFF_SM;

    const int tid  = threadIdx.x;
    const int nthr = blockDim.x;

    // ---- init: zero padded regions ----
    for (int i = tid; i < 51200; i += nthr) sW[i] = 0.0f;
    for (int i = tid; i < 512; i += nthr) { sB[i] = 0.0f; sWx[i] = 0.0f; sW2[i] = 0.0f; }
    if (tid < 4) sSm[tid] = W_hh2[tid];
    else if (tid < 8) sSm[tid] = b_ih2[tid-4] + b_hh2[tid-4];
    __syncthreads();

    // ---- fill rearranged weights ----
    // W_hh1 [400,100]: row j = g*100+u, col kp.  Unit u -> slot s=u>>5, lane l=u&31,
    // slot-pair sp=s>>1, half h=s&1.  smem idx: ((g*2+sp)*100+kp)*64 + 2*l + h
    for (int i = tid; i < 40000; i += nthr) {
        int j = i / 100, kp = i % 100;
        int g = j / 100, u = j % 100;
        int s = u >> 5, l = u & 31;
        int sp = s >> 1, h = s & 1;
        sW[((g*2 + sp)*100 + kp)*64 + 2*l + h] = W_hh1[i];
    }
    for (int i = tid; i < 400; i += nthr) {
        int g = i / 100, u = i % 100;
        sB[g*128 + u]  = b_ih1[i] + b_hh1[i];
        sWx[g*128 + u] = W_ih1[i];          // W_ih1 is [400,1]
    }
    for (int i = tid; i < 400; i += nthr) {
        int m = i / 100, u = i % 100;
        sW2[m*128 + u] = W_ih2[i];
    }
    __syncthreads();

    const int warp = tid >> 5, lane = tid & 31;
    const int base_elem = blockIdx.x * EPC + warp * RB;

    // ---- per-lane cached constants ----
    float biasc[4][2][2], wxc[4][2][2];
    #pragma unroll
    for (int g = 0; g < 4; ++g)
        #pragma unroll
        for (int sp = 0; sp < 2; ++sp)
            #pragma unroll
            for (int h = 0; h < 2; ++h) {
                int up = (2*sp + h)*32 + lane;
                biasc[g][sp][h] = sB[g*128 + up];
                wxc[g][sp][h]   = sWx[g*128 + up];
            }
    float w2c[4][4];
    #pragma unroll
    for (int m = 0; m < 4; ++m)
        #pragma unroll
        for (int s = 0; s < 4; ++s)
            w2c[m][s] = sW2[m*128 + s*32 + lane];
    float whh2c[4], b2c[4];
    #pragma unroll
    for (int m = 0; m < 4; ++m) { whh2c[m] = sSm[m]; b2c[m] = sSm[4+m]; }

    // ---- state ----
    float h1[4][RB], c1[4][RB];
    #pragma unroll
    for (int s = 0; s < 4; ++s)
        #pragma unroll
        for (int r = 0; r < RB; ++r) { h1[s][r] = 0.0f; c1[s][r] = 0.0f; }
    float h2v = 0.0f, c2v = 0.0f;

    const float* wb = sW + 2*lane;

    // prefetch first input block: lane holds x at time t0+lane
    float xv[RB], xnx[RB];
    #pragma unroll
    for (int r = 0; r < RB; ++r) {
        int e = base_elem + r;
        xnx[r] = (e < BB) ? input[(long)e*TT + lane] : 0.0f;
    }

    for (int t0 = 0; t0 < TT; t0 += 32) {
        #pragma unroll
        for (int r = 0; r < RB; ++r) xv[r] = xnx[r];
        if (t0 + 32 < TT) {
            #pragma unroll
            for (int r = 0; r < RB; ++r) {
                int e = base_elem + r;
                xnx[r] = (e < BB) ? input[(long)e*TT + t0 + 32 + lane] : 0.0f;
            }
        }

        #pragma unroll 1
        for (int tt = 0; tt < 32; ++tt) {
            // broadcast x_t per element
            float xr[RB];
            #pragma unroll
            for (int r = 0; r < RB; ++r)
                xr[r] = __shfl_sync(0xffffffffu, xv[r], tt);

            // init gate accumulators: packed (slot 2sp | slot 2sp+1)
            ull acc[2][4][RB];
            #pragma unroll
            for (int sp = 0; sp < 2; ++sp)
                #pragma unroll
                for (int g = 0; g < 4; ++g)
                    #pragma unroll
                    for (int r = 0; r < RB; ++r)
                        acc[sp][g][r] = pk2(fmaf(wxc[g][sp][0], xr[r], biasc[g][sp][0]),
                                            fmaf(wxc[g][sp][1], xr[r], biasc[g][sp][1]));

            // hidden matvec: gates += W_hh1 * h1
            #pragma unroll
            for (int sq = 0; sq < 4; ++sq) {
                const int mmax = (sq == 3) ? 4 : 32;
                #pragma unroll 4
                for (int m = 0; m < mmax; ++m) {
                    ull hb2[RB];
                    #pragma unroll
                    for (int r = 0; r < RB; ++r) {
                        float hv = __shfl_sync(0xffffffffu, h1[sq][r], m);
                        hb2[r] = pk2(hv, hv);
                    }
                    const int kp = sq*32 + m;
                    #pragma unroll
                    for (int g = 0; g < 4; ++g)
                        #pragma unroll
                        for (int sp = 0; sp < 2; ++sp) {
                            ull w2 = *reinterpret_cast<const ull*>(wb + ((g*2 + sp)*100 + kp)*64);
                            #pragma unroll
                            for (int r = 0; r < RB; ++r)
                                acc[sp][g][r] = fma2(w2, hb2[r], acc[sp][g][r]);
                        }
                }
            }

            // activations + cell update (layer 1)
            #pragma unroll
            for (int sp = 0; sp < 2; ++sp)
                #pragma unroll
                for (int r = 0; r < RB; ++r) {
                    float i0, i1, f0, f1, g0, g1, o0, o1;
                    upk2(acc[sp][0][r], i0, i1);
                    upk2(acc[sp][1][r], f0, f1);
                    upk2(acc[sp][2][r], g0, g1);
                    upk2(acc[sp][3][r], o0, o1);
                    const int s0 = 2*sp, s1 = 2*sp + 1;
                    float c;
                    c = sigf(f0)*c1[s0][r] + sigf(i0)*tahf(g0);
                    c1[s0][r] = c;
                    h1[s0][r] = sigf(o0)*tahf(c);
                    c = sigf(f1)*c1[s1][r] + sigf(i1)*tahf(g1);
                    c1[s1][r] = c;
                    h1[s1][r] = sigf(o1)*tahf(c);
                }

            // layer 2: z[m][r] = sum_k W_ih2[m][k] * h1[k]
            float p[4][RB];
            #pragma unroll
            for (int m = 0; m < 4; ++m)
                #pragma unroll
                for (int r = 0; r < RB; ++r) p[m][r] = 0.0f;
            #pragma unroll
            for (int m = 0; m < 4; ++m)
                #pragma unroll
                for (int s = 0; s < 4; ++s)
                    #pragma unroll
                    for (int r = 0; r < RB; ++r)
                        p[m][r] = fmaf(w2c[m][s], h1[s][r], p[m][r]);
            #pragma unroll
            for (int off = 16; off >= 1; off >>= 1)
                #pragma unroll
                for (int m = 0; m < 4; ++m)
                    #pragma unroll
                    for (int r = 0; r < RB; ++r)
                        p[m][r] += __shfl_xor_sync(0xffffffffu, p[m][r], off);

            // lane r owns element r's scalar LSTM2 state
            float z0 = 0.0f, z1 = 0.0f, z2 = 0.0f, z3 = 0.0f;
            #pragma unroll
            for (int r = 0; r < RB; ++r)
                if (lane == r) { z0 = p[0][r]; z1 = p[1][r]; z2 = p[2][r]; z3 = p[3][r]; }

            if (lane < RB) {
                float i2 = sigf(z0 + whh2c[0]*h2v + b2c[0]);
                float f2 = sigf(z1 + whh2c[1]*h2v + b2c[1]);
                float g2 = tahf(z2 + whh2c[2]*h2v + b2c[2]);
                float o2 = sigf(z3 + whh2c[3]*h2v + b2c[3]);
                c2v = f2*c2v + i2*g2;
                h2v = o2 * tahf(c2v);
                int e = base_elem + lane;
                if (e < BB) out[(long)e*TT + t0 + tt] = h2v;
            }
        }
    }
}

extern "C" void kernel_launch(void* const* d_in, const int* in_sizes, int n_in,
                              void* d_out, int out_size) {
    const float* input = (const float*)d_in[0];
    const float* W_ih1 = (const float*)d_in[1];
    const float* W_hh1 = (const float*)d_in[2];
    const float* b_ih1 = (const float*)d_in[3];
    const float* b_hh1 = (const float*)d_in[4];
    const float* W_ih2 = (const float*)d_in[5];
    const float* W_hh2 = (const float*)d_in[6];
    const float* b_ih2 = (const float*)d_in[7];
    const float* b_hh2 = (const float*)d_in[8];
    float* out = (float*)d_out;

    cudaFuncSetAttribute(lstm2_kernel, cudaFuncAttributeMaxDynamicSharedMemorySize, SMEM_BYTES);

    const int ctas = (BB + EPC - 1) / EPC;   // 147
    lstm2_kernel<<<ctas, WARPS*32, SMEM_BYTES>>>(
        input, W_ih1, W_hh1, b_ih1, b_hh1, W_ih2, W_hh2, b_ih2, b_hh2, out);
}

// round 4
// speedup vs baseline: 1.0533x; 1.0533x over previous
#include <cuda_runtime.h>
#include <cstdint>

typedef unsigned long long ull;

#define RB 7
#define WARPS 4
#define NTHR (WARPS*32)
#define EPC (WARPS*RB)   // 28
#define BB 4096
#define TT 2048

// smem float offsets
#define OFF_WP 0                 // [100 k][7 s][64 = 2*lane+half] -> 44800 floats
#define OFF_BI 44800             // [7][64] packed (bsum[p], bsum[p+200])
#define OFF_WX 45248             // [7][64] packed (Wih1[p], Wih1[p+200])
#define OFF_HD 45696             // [WARPS][RB][100] ull -> 4*7*100*2 = 5600 floats
#define SMEM_FLOATS (45696 + 5600)
#define SMEM_BYTES (SMEM_FLOATS*4)

__device__ __forceinline__ ull pk2(float lo, float hi) {
    ull r; asm("mov.b64 %0, {%1, %2};" : "=l"(r) : "f"(lo), "f"(hi)); return r;
}
__device__ __forceinline__ void upk2(ull v, float& lo, float& hi) {
    asm("mov.b64 {%0, %1}, %2;" : "=f"(lo), "=f"(hi) : "l"(v));
}
__device__ __forceinline__ ull fma2(ull a, ull b, ull c) {
    ull d; asm("fma.rn.f32x2 %0, %1, %2, %3;" : "=l"(d) : "l"(a), "l"(b), "l"(c)); return d;
}
__device__ __forceinline__ float sigf(float x) {
    float e = __expf(-x);
    return __fdividef(1.0f, 1.0f + e);
}
__device__ __forceinline__ float tahf(float x) {
    float a = fabsf(x);
    float E = __expf(2.0f * a);
    float t = 1.0f - __fdividef(2.0f, E + 1.0f);
    return (x < 0.0f) ? -t : t;
}

__global__ __launch_bounds__(NTHR, 1)
void lstm2_kernel(const float* __restrict__ input,
                  const float* __restrict__ W_ih1,
                  const float* __restrict__ W_hh1,
                  const float* __restrict__ b_ih1,
                  const float* __restrict__ b_hh1,
                  const float* __restrict__ W_ih2,
                  const float* __restrict__ W_hh2,
                  const float* __restrict__ b_ih2,
                  const float* __restrict__ b_hh2,
                  float* __restrict__ out)
{
    extern __shared__ float smem[];
    float* sWP = smem + OFF_WP;
    float* sBI = smem + OFF_BI;
    float* sWX = smem + OFF_WX;

    const int tid  = threadIdx.x;

    // ---- zero all smem regions (incl. h-dup so first step sees h=0) ----
    for (int i = tid; i < SMEM_FLOATS; i += NTHR) smem[i] = 0.0f;
    __syncthreads();

    // ---- fill flattened-pair weights ----
    // pair p (0..199): lo = flat row p of W_hh1, hi = flat row p+200.
    //   p = u        -> (i_u, g_u);  p = 100+u -> (f_u, o_u)
    // smem: sWP[(k*7 + s)*64 + 2*l + h], s = p>>5, l = p&31
    for (int i = tid; i < 20000; i += NTHR) {
        int p = i / 100, k = i % 100;
        int s = p >> 5, l = p & 31;
        sWP[(k*7 + s)*64 + 2*l    ] = W_hh1[p*100 + k];
        sWP[(k*7 + s)*64 + 2*l + 1] = W_hh1[(p+200)*100 + k];
    }
    for (int p = tid; p < 200; p += NTHR) {
        int s = p >> 5, l = p & 31;
        sBI[s*64 + 2*l    ] = b_ih1[p]     + b_hh1[p];
        sBI[s*64 + 2*l + 1] = b_ih1[p+200] + b_hh1[p+200];
        sWX[s*64 + 2*l    ] = W_ih1[p];        // W_ih1 is [400,1]
        sWX[s*64 + 2*l + 1] = W_ih1[p+200];
    }
    __syncthreads();

    const int warp = tid >> 5, lane = tid & 31;
    const int base_elem = blockIdx.x * EPC + warp * RB;

    // per-warp private h duplicate buffer: [r][k] of (h,h)
    ull* hd = reinterpret_cast<ull*>(smem + OFF_HD) + (warp * RB) * 100;

    // ---- layer-2 per-lane constants (from gmem; loop-invariant) ----
    float w2c[4][4];
    #pragma unroll
    for (int m = 0; m < 4; ++m)
        #pragma unroll
        for (int s = 0; s < 4; ++s) {
            int u = s*32 + lane;
            w2c[m][s] = (u < 100) ? W_ih2[m*100 + u] : 0.0f;
        }
    float whh2c[4], b2c2[4];
    #pragma unroll
    for (int m = 0; m < 4; ++m) { whh2c[m] = W_hh2[m]; b2c2[m] = b_ih2[m] + b_hh2[m]; }

    // ---- state ----
    float h1[4][RB], c1[4][RB];
    #pragma unroll
    for (int s = 0; s < 4; ++s)
        #pragma unroll
        for (int r = 0; r < RB; ++r) { h1[s][r] = 0.0f; c1[s][r] = 0.0f; }
    float h2v = 0.0f, c2v = 0.0f;

    const float* wk_base = sWP + 2*lane;

    // prefetch input: lane holds x at time t0+lane for each of its RB elems
    float xv[RB], xnx[RB];
    #pragma unroll
    for (int r = 0; r < RB; ++r) {
        int e = base_elem + r;
        xnx[r] = (e < BB) ? input[(long)e*TT + lane] : 0.0f;
    }

    for (int t0 = 0; t0 < TT; t0 += 32) {
        #pragma unroll
        for (int r = 0; r < RB; ++r) xv[r] = xnx[r];
        if (t0 + 32 < TT) {
            #pragma unroll
            for (int r = 0; r < RB; ++r) {
                int e = base_elem + r;
                xnx[r] = (e < BB) ? input[(long)e*TT + t0 + 32 + lane] : 0.0f;
            }
        }

        #pragma unroll 1
        for (int tt = 0; tt < 32; ++tt) {
            // broadcast x_t, init accumulators: acc = bias + Wih1 * x
            ull x2[RB];
            #pragma unroll
            for (int r = 0; r < RB; ++r) {
                float xr = __shfl_sync(0xffffffffu, xv[r], tt);
                x2[r] = pk2(xr, xr);
            }
            ull acc[7][RB];
            #pragma unroll
            for (int s = 0; s < 7; ++s) {
                ull wx = *reinterpret_cast<const ull*>(sWX + s*64 + 2*lane);
                ull bb = *reinterpret_cast<const ull*>(sBI + s*64 + 2*lane);
                #pragma unroll
                for (int r = 0; r < RB; ++r)
                    acc[s][r] = fma2(wx, x2[r], bb);
            }

            // hidden matvec over k (h broadcast from warp-private smem)
            const float* wkp = wk_base;
            #pragma unroll 2
            for (int k = 0; k < 100; k += 2) {
                ull hb0[RB], hb1[RB];
                #pragma unroll
                for (int r = 0; r < RB; ++r) {
                    ulonglong2 hv = *reinterpret_cast<const ulonglong2*>(hd + r*100 + k);
                    hb0[r] = hv.x; hb1[r] = hv.y;
                }
                #pragma unroll
                for (int s = 0; s < 7; ++s) {
                    ull w0 = *reinterpret_cast<const ull*>(wkp + s*64);
                    #pragma unroll
                    for (int r = 0; r < RB; ++r)
                        acc[s][r] = fma2(w0, hb0[r], acc[s][r]);
                }
                #pragma unroll
                for (int s = 0; s < 7; ++s) {
                    ull w1 = *reinterpret_cast<const ull*>(wkp + (7+s)*64);
                    #pragma unroll
                    for (int r = 0; r < RB; ++r)
                        acc[s][r] = fma2(w1, hb1[r], acc[s][r]);
                }
                wkp += 14*64;
            }

            // activations: own pair (i_u, g_u) at p=u; partner (f_u, o_u) at p=100+u
            // partner lane = (l+4)&31, register acc[s+3] (l<28) or acc[s+4] (l>=28)
            const int src = (lane + 4) & 31;
            #pragma unroll
            for (int s = 0; s < 3; ++s) {
                #pragma unroll
                for (int r = 0; r < RB; ++r) {
                    float ii, gg; upk2(acc[s][r], ii, gg);
                    float pa0, pa1, pb0, pb1;
                    upk2(acc[s+3][r], pa0, pa1);
                    upk2(acc[s+4][r], pb0, pb1);
                    float fa = __shfl_sync(0xffffffffu, pa0, src);
                    float oa = __shfl_sync(0xffffffffu, pa1, src);
                    float fb = __shfl_sync(0xffffffffu, pb0, src);
                    float ob = __shfl_sync(0xffffffffu, pb1, src);
                    float fv = (lane < 28) ? fa : fb;
                    float ov = (lane < 28) ? oa : ob;
                    float c = sigf(fv)*c1[s][r] + sigf(ii)*tahf(gg);
                    c1[s][r] = c;
                    float h = sigf(ov)*tahf(c);
                    h1[s][r] = h;
                    hd[r*100 + s*32 + lane] = pk2(h, h);
                }
            }
            // s = 3: units 96..99 live on lanes 0..3; partner in acc[6]
            #pragma unroll
            for (int r = 0; r < RB; ++r) {
                float ii, gg; upk2(acc[3][r], ii, gg);
                float pa0, pa1; upk2(acc[6][r], pa0, pa1);
                float fv = __shfl_sync(0xffffffffu, pa0, src);
                float ov = __shfl_sync(0xffffffffu, pa1, src);
                if (lane < 4) {
                    float c = sigf(fv)*c1[3][r] + sigf(ii)*tahf(gg);
                    c1[3][r] = c;
                    float h = sigf(ov)*tahf(c);
                    h1[3][r] = h;
                    hd[r*100 + 96 + lane] = pk2(h, h);
                }
            }
            __syncwarp();

            // layer 2: z[m][r] = sum_u W_ih2[m][u] * h1[u]
            float p[4][RB];
            #pragma unroll
            for (int m = 0; m < 4; ++m)
                #pragma unroll
                for (int r = 0; r < RB; ++r) p[m][r] = 0.0f;
            #pragma unroll
            for (int m = 0; m < 4; ++m)
                #pragma unroll
                for (int s = 0; s < 4; ++s)
                    #pragma unroll
                    for (int r = 0; r < RB; ++r)
                        p[m][r] = fmaf(w2c[m][s], h1[s][r], p[m][r]);
            #pragma unroll
            for (int off = 16; off >= 1; off >>= 1)
                #pragma unroll
                for (int m = 0; m < 4; ++m)
                    #pragma unroll
                    for (int r = 0; r < RB; ++r)
                        p[m][r] += __shfl_xor_sync(0xffffffffu, p[m][r], off);

            // lane r owns element r's scalar LSTM2 state
            float z0 = 0.0f, z1 = 0.0f, z2 = 0.0f, z3 = 0.0f;
            #pragma unroll
            for (int r = 0; r < RB; ++r)
                if (lane == r) { z0 = p[0][r]; z1 = p[1][r]; z2 = p[2][r]; z3 = p[3][r]; }

            if (lane < RB) {
                float i2 = sigf(z0 + whh2c[0]*h2v + b2c2[0]);
                float f2 = sigf(z1 + whh2c[1]*h2v + b2c2[1]);
                float g2 = tahf(z2 + whh2c[2]*h2v + b2c2[2]);
                float o2 = sigf(z3 + whh2c[3]*h2v + b2c2[3]);
                c2v = f2*c2v + i2*g2;
                h2v = o2 * tahf(c2v);
                int e = base_elem + lane;
                if (e < BB) out[(long)e*TT + t0 + tt] = h2v;
            }
        }
    }
}

extern "C" void kernel_launch(void* const* d_in, const int* in_sizes, int n_in,
                              void* d_out, int out_size) {
    const float* input = (const float*)d_in[0];
    const float* W_ih1 = (const float*)d_in[1];
    const float* W_hh1 = (const float*)d_in[2];
    const float* b_ih1 = (const float*)d_in[3];
    const float* b_hh1 = (const float*)d_in[4];
    const float* W_ih2 = (const float*)d_in[5];
    const float* W_hh2 = (const float*)d_in[6];
    const float* b_ih2 = (const float*)d_in[7];
    const float* b_hh2 = (const float*)d_in[8];
    float* out = (float*)d_out;

    cudaFuncSetAttribute(lstm2_kernel, cudaFuncAttributeMaxDynamicSharedMemorySize, SMEM_BYTES);

    const int ctas = (BB + EPC - 1) / EPC;   // 147
    lstm2_kernel<<<ctas, NTHR, SMEM_BYTES>>>(
        input, W_ih1, W_hh1, b_ih1, b_hh1, W_ih2, W_hh2, b_ih2, b_hh2, out);
}